// round 3
// baseline (speedup 1.0000x reference)
#include <cuda_runtime.h>

// Problem constants (LinearDiffusion_2860448219950)
#define NN   8192
#define HH   4
#define EE   131072
#define DD   64
#define TBL  (1 << 20)
#define TBLM (TBL - 1)

// ---------------- device scratch (no allocations allowed) ----------------
__device__ unsigned int g_ht_key[TBL];   // 4 MB
__device__ unsigned int g_ht_prio[TBL];  // 4 MB
__device__ int          g_deg[NN];
__device__ int          g_rowstart[NN + 1];
__device__ int          g_rowfill[NN];
__device__ float        g_rowsum[NN * HH];
__device__ int          g_nnz;
__device__ int          g_tmp_i[2 * EE];
__device__ int          g_tmp_j[2 * EE];
__device__ int          g_tmp_k[2 * EE];
__device__ int          g_cols[2 * EE];
__device__ float4       g_vals[2 * EE];  // per-head normalized values
__device__ float        g_x[2][NN * DD]; // ping-pong SpMM buffers, (H,N,16)-flat layout

__device__ __forceinline__ unsigned int hash_key(unsigned int key) {
    return (key * 2654435761u) >> 12;  // top 20 bits of 32-bit product
}

// ---------------- 0: zero scratch ----------------
__global__ void k_zero() {
    int t = blockIdx.x * blockDim.x + threadIdx.x;
    int stride = gridDim.x * blockDim.x;
    for (int s = t; s < TBL; s += stride) { g_ht_key[s] = 0xFFFFFFFFu; g_ht_prio[s] = 0u; }
    for (int s = t; s < NN;  s += stride) { g_deg[s] = 0; g_rowfill[s] = 0; }
    for (int s = t; s < NN * HH; s += stride) g_rowsum[s] = 0.f;
    if (t == 0) g_nnz = 0;
}

// ---------------- 1: hash insert with last-write-wins priority ----------------
// Pass 0: entry (src[k], dst[k]); Pass 1 (applied AFTER): entry (dst[k], src[k]).
// Winner at an (i,j) slot = max priority = ((pass<<17)|k)+1  (later pass, later k wins).
__global__ void k_insert(const int* __restrict__ src, const int* __restrict__ dst) {
    int t = blockIdx.x * blockDim.x + threadIdx.x;
    if (t >= 2 * EE) return;
    int pass = (t >= EE) ? 1 : 0;
    int k = pass ? (t - EE) : t;
    int i = pass ? dst[k] : src[k];
    int j = pass ? src[k] : dst[k];
    unsigned int key  = ((unsigned int)i << 13) | (unsigned int)j;
    unsigned int prio = (((unsigned int)pass << 17) | (unsigned int)k) + 1u;
    unsigned int s = hash_key(key) & TBLM;
    while (true) {
        unsigned int old = atomicCAS(&g_ht_key[s], 0xFFFFFFFFu, key);
        if (old == 0xFFFFFFFFu || old == key) {
            atomicMax(&g_ht_prio[s], prio);
            break;
        }
        s = (s + 1) & TBLM;
    }
}

// ---------------- 2: winners -> COO + degree + per-head rowsum ----------------
__global__ void k_winner(const int* __restrict__ src, const int* __restrict__ dst,
                         const float* __restrict__ e) {
    int t = blockIdx.x * blockDim.x + threadIdx.x;
    if (t >= 2 * EE) return;
    int pass = (t >= EE) ? 1 : 0;
    int k = pass ? (t - EE) : t;
    int i = pass ? dst[k] : src[k];
    int j = pass ? src[k] : dst[k];
    unsigned int key  = ((unsigned int)i << 13) | (unsigned int)j;
    unsigned int prio = (((unsigned int)pass << 17) | (unsigned int)k) + 1u;
    unsigned int s = hash_key(key) & TBLM;
    while (g_ht_key[s] != key) s = (s + 1) & TBLM;
    if (g_ht_prio[s] != prio) return;  // not the winning write for this (i,j)
    int idx = atomicAdd(&g_nnz, 1);
    g_tmp_i[idx] = i;
    g_tmp_j[idx] = j;
    g_tmp_k[idx] = k;
    atomicAdd(&g_deg[i], 1);
#pragma unroll
    for (int h = 0; h < HH; h++)
        atomicAdd(&g_rowsum[i * HH + h], e[h * EE + k]);
}

// ---------------- 3: exclusive scan of degrees -> CSR row_start ----------------
__global__ void k_scan() {
    __shared__ int ssum[1024];
    int tid = threadIdx.x;               // 1024 threads, 8 rows each
    int base = tid * 8;
    int local[8];
    int s = 0;
#pragma unroll
    for (int q = 0; q < 8; q++) { local[q] = s; s += g_deg[base + q]; }
    ssum[tid] = s;
    __syncthreads();
    for (int off = 1; off < 1024; off <<= 1) {
        int v = (tid >= off) ? ssum[tid - off] : 0;
        __syncthreads();
        ssum[tid] += v;
        __syncthreads();
    }
    int excl = (tid == 0) ? 0 : ssum[tid - 1];
#pragma unroll
    for (int q = 0; q < 8; q++) g_rowstart[base + q] = excl + local[q];
    if (tid == 1023) g_rowstart[NN] = ssum[1023];
}

// ---------------- 4: CSR fill with normalized per-head values ----------------
__global__ void k_fill(const float* __restrict__ e) {
    int t = blockIdx.x * blockDim.x + threadIdx.x;
    if (t >= g_nnz) return;
    int i = g_tmp_i[t];
    int j = g_tmp_j[t];
    int k = g_tmp_k[t];
    int pos = g_rowstart[i] + atomicAdd(&g_rowfill[i], 1);
    g_cols[pos] = j;
    float4 v;
    v.x = e[0 * EE + k] / g_rowsum[i * HH + 0];
    v.y = e[1 * EE + k] / g_rowsum[i * HH + 1];
    v.z = e[2 * EE + k] / g_rowsum[i * HH + 2];
    v.w = e[3 * EE + k] / g_rowsum[i * HH + 3];
    g_vals[pos] = v;
}

// ---------------- 5: result := h (flat copy; layouts are byte-identical) ----------------
__global__ void k_copy(const float* __restrict__ src, float* __restrict__ dst) {
    int t = blockIdx.x * blockDim.x + threadIdx.x;
    if (t < NN * DD) dst[t] = src[t];
}

// ---------------- 6: SpMM  xout = A_norm @ xin ; res += xout * invf ----------------
// State layout is (H, N, 16) contiguous == flat h / flat out (reference uses raw
// reshape, so head hh owns flat slice [hh*N*16, (hh+1)*N*16)).
// 64 threads per row: head = (tid&63)>>4, feature dim d = tid&15.
// Value load is scalar (lane's head component only): 16 lanes of a head
// broadcast-hit the same 4B word instead of each pulling the full float4.
__global__ void k_spmm(const float* __restrict__ xin, float* __restrict__ xout,
                       float* __restrict__ res, float invf) {
    int row = blockIdx.x * 2 + (threadIdx.x >> 6);
    int c = threadIdx.x & 63;
    int head = c >> 4;
    int d = c & 15;
    int hbase = head << 17;   // head * N * 16 = head * 131072
    int s = g_rowstart[row];
    int epos = g_rowstart[row + 1];
    const float* vals = (const float*)g_vals;
    float acc = 0.f;
    for (int t = s; t < epos; t++) {
        int j = g_cols[t];
        float v = vals[t * 4 + head];
        acc += v * __ldg(&xin[hbase + (j << 4) + d]);
    }
    int o = hbase + (row << 4) + d;
    xout[o] = acc;
    res[o] += acc * invf;
}

// ---------------- launch ----------------
extern "C" void kernel_launch(void* const* d_in, const int* in_sizes, int n_in,
                              void* d_out, int out_size) {
    const float* h   = (const float*)d_in[0];
    const float* e   = (const float*)d_in[1];
    const int*   src = (const int*)d_in[2];
    const int*   dst = (const int*)d_in[3];
    float* out = (float*)d_out;

    k_zero<<<512, 256>>>();
    k_insert<<<(2 * EE + 255) / 256, 256>>>(src, dst);
    k_winner<<<(2 * EE + 255) / 256, 256>>>(src, dst, e);
    k_scan<<<1, 1024>>>();
    k_fill<<<(2 * EE + 255) / 256, 256>>>(e);
    k_copy<<<(NN * DD + 255) / 256, 256>>>(h, out);

    float* xa;  float* xb;
    cudaGetSymbolAddress((void**)&xa, g_x);
    xb = xa + NN * DD;

    const float invf[6] = {1.0f, 0.5f, 1.0f / 6.0f, 1.0f / 24.0f, 1.0f / 120.0f, 1.0f / 720.0f};
    const float* cur = h;
    float* bufs[2] = {xa, xb};
    for (int it = 0; it < 6; it++) {
        float* nxt = bufs[it & 1];
        k_spmm<<<NN / 2, 128>>>(cur, nxt, out, invf[it]);
        cur = nxt;
    }
}